// round 11
// baseline (speedup 1.0000x reference)
#include <cuda_runtime.h>
#include <cstdint>
#include <cstddef>

// Problem constants
#define NUM_LUT 3
#define GDIM    1024      // G = IN_F / VEC
#define OUTF    4096
#define SLUT    16
#define VEC     4
#define NGRP    32        // NG = IN_F / GROUP (GROUP = 32 g's)

// Tiling: block = 8 warps; each warp owns 8 consecutive o's; block loops 16 g's.
#define NTHREADS 256
#define O_PER_WARP 8
#define OTILE (8 * O_PER_WARP)   // 64 o per block
#define GTILE_J 16               // g's per block (16 | 32 -> single quant group per block)

// Output staging tile: [64 o][stride 68 words]; row holds 16 j * 4 part = 64
// floats + 4 pad words. 68 mod 32 == 4 => STS bank = (o_sub*4 + part) mod 32,
// distinct for all 32 lanes of a warp (conflict-free); flush phases likewise.
#define SROW 68

// Per-LUT argmax over 16 gate values spread across a quad (4 floats/lane):
//  1) exact local first-max scan over this lane's 4 values
//  2) quad max by VALUE only: 2x shfl.bfly + fmaxf (bit-exact, NaN-free data)
//  3) ballot (full-warp uniform mask) of lanes matching the quad max;
//     lowest set lane in my quad = exact first-occurrence winner
//  4) one shfl.idx fetches the winner's local index
// Bit-exact vs jnp.argmax first-index tie semantics.
// cbL = codebook + (L*GDIM+g0)*64 + part  (precomputed); offset = j*64 + gidx*4.
#define DO_LUT(v, cbL, j, accv)                                               \
    {                                                                         \
        float m = (v).x; int mi = 0;                                          \
        if ((v).y > m) { m = (v).y; mi = 1; }                                 \
        if ((v).z > m) { m = (v).z; mi = 2; }                                 \
        if ((v).w > m) { m = (v).w; mi = 3; }                                 \
        float q = fmaxf(m, __shfl_xor_sync(0xffffffffu, m, 1));               \
        q = fmaxf(q, __shfl_xor_sync(0xffffffffu, q, 2));                     \
        const unsigned bal = __ballot_sync(0xffffffffu, m == q);              \
        const unsigned nib = (bal >> (lane & 28)) & 0xFu;                     \
        const int wl = (lane & 28) + (__ffs(nib) - 1);                        \
        const int wmi = __shfl_sync(0xffffffffu, mi, wl);                     \
        const int gidx = ((wl & 3) << 2) | wmi;                               \
        (accv) += __ldg((cbL) + ((j) << 6) + (gidx << 2));                    \
    }

__global__ void __launch_bounds__(NTHREADS, 8)
recon_kernel(const float* __restrict__ gate,
             const float* __restrict__ codebook,
             const float* __restrict__ scales,
             const int*   __restrict__ zeros,
             float*       __restrict__ out)
{
    __shared__ float otile[OTILE * SROW];   // 17408 B

    const int tid    = threadIdx.x;
    const int wid    = tid >> 5;
    const int lane   = tid & 31;
    const int part   = lane & 3;              // which 16B quarter of the 64B gate row
    const int o_sub  = lane >> 2;             // which of the warp's 8 o's

    const int o0_blk = blockIdx.x * OTILE;
    const int o0     = o0_blk + wid * O_PER_WARP;   // warp's first o
    const int o      = o0 + o_sub;
    const int o_loc  = wid * O_PER_WARP + o_sub;    // 0..63 within block
    const int g0     = blockIdx.y * GTILE_J;
    const int ng     = blockIdx.y >> 1;       // quant group (16*2 = 32 g's per group)

    const float sc   = scales[o * NGRP + ng];
    const float bias = -((float)zeros[o * NGRP + ng]) * sc;  // out = acc*sc + bias

    // Gate base pointers (float4 units). For fixed (l,g): warp covers
    // o0..o0+7 -> one contiguous 512B chunk; lane q reads float4 #q.
    const float4* gp0 = reinterpret_cast<const float4*>(gate) +
        (((size_t)0 * GDIM + g0) * OUTF + o0) * (SLUT / 4) + lane;
    const float4* gp1 = reinterpret_cast<const float4*>(gate) +
        (((size_t)1 * GDIM + g0) * OUTF + o0) * (SLUT / 4) + lane;
    const float4* gp2 = reinterpret_cast<const float4*>(gate) +
        (((size_t)2 * GDIM + g0) * OUTF + o0) * (SLUT / 4) + lane;
    const size_t gstep = (size_t)OUTF * SLUT / 4;   // 16384 float4 per g

    // Per-LUT codebook base for this block's g-range and this lane's part.
    const float* cb0 = codebook + ((size_t)(0 * GDIM) + g0) * (SLUT * VEC) + part;
    const float* cb1 = codebook + ((size_t)(1 * GDIM) + g0) * (SLUT * VEC) + part;
    const float* cb2 = codebook + ((size_t)(2 * GDIM) + g0) * (SLUT * VEC) + part;

    float* myrow = &otile[o_loc * SROW + part];     // + j*4 per step

    #pragma unroll 2
    for (int j = 0; j < GTILE_J; ++j) {
        // Issue all three contiguous 512B streaming loads up front
        const float4 v0 = __ldcs(gp0 + (size_t)j * gstep);
        const float4 v1 = __ldcs(gp1 + (size_t)j * gstep);
        const float4 v2 = __ldcs(gp2 + (size_t)j * gstep);

        float acc = 0.0f;
        DO_LUT(v0, cb0, j, acc)
        DO_LUT(v1, cb1, j, acc)
        DO_LUT(v2, cb2, j, acc)

        // Stage into smem (conflict-free); flushed coalesced at block end.
        myrow[j * 4] = fmaf(acc, sc, bias);
    }

    __syncthreads();

    // Flush: 1024 float4 slots; thread t handles 4 slots. Each 8-lane group
    // writes one full, aligned 128B global line: zero partial sectors, no RMW.
    #pragma unroll
    for (int t = 0; t < 4; ++t) {
        const int idx = tid + t * NTHREADS;    // 0..1023
        const int ol  = idx >> 4;              // 0..63
        const int jj  = idx & 15;              // 0..15
        const float4 v = *reinterpret_cast<const float4*>(&otile[ol * SROW + jj * 4]);
        __stcs(reinterpret_cast<float4*>(out) +
               (size_t)(o0_blk + ol) * (GDIM) + g0 + jj, v);
    }
}

extern "C" void kernel_launch(void* const* d_in, const int* in_sizes, int n_in,
                              void* d_out, int out_size) {
    const float* gate     = (const float*)d_in[0];  // [3,1024,4096,16] f32
    const float* codebook = (const float*)d_in[1];  // [3,1024,16,4]   f32
    const float* scales   = (const float*)d_in[2];  // [4096,32]       f32
    const int*   zeros    = (const int*)  d_in[3];  // [4096,32]       i32
    float*       out      = (float*)d_out;          // [4096,4096]     f32

    (void)in_sizes; (void)n_in; (void)out_size;

    dim3 grid(OUTF / OTILE, GDIM / GTILE_J);   // (64, 64) = 4096 blocks
    recon_kernel<<<grid, NTHREADS>>>(gate, codebook, scales, zeros, out);
}

// round 14
// speedup vs baseline: 1.0303x; 1.0303x over previous
#include <cuda_runtime.h>
#include <cstdint>
#include <cstddef>

// Problem constants
#define NUM_LUT 3
#define GDIM    1024      // G = IN_F / VEC
#define OUTF    4096
#define SLUT    16
#define VEC     4
#define NGRP    32        // NG = IN_F / GROUP (GROUP = 32 g's)

// Tiling: block = 8 warps; each warp owns 8 consecutive o's; block loops 8 g's.
// (GTILE_J=8 is frozen: R10 showed 16 regresses via longer barrier phases.)
#define NTHREADS 256
#define O_PER_WARP 8
#define OTILE (8 * O_PER_WARP)   // 64 o per block
#define GTILE_J 8                // g's per block (8 | 32 -> single quant group per block)

// Output staging tile: [64 o][stride 36 words]; row holds 8 j * 4 part = 32
// floats + 4 pad words. Stride 36 => STS bank = (o_sub*4 + part) mod 32,
// distinct for all 32 lanes of a warp (conflict-free); flush phases likewise.
#define SROW 36

// Per-LUT argmax over 16 gate values spread across a quad (4 floats/lane):
//  1) exact local first-max scan over this lane's 4 values
//  2) quad max by VALUE only: 2x shfl.bfly + fmaxf (bit-exact, NaN-free data)
//  3) ballot (full-warp uniform mask) of lanes matching the quad max;
//     lowest set lane in my quad = exact first-occurrence winner
//  4) one shfl.idx fetches the winner's local index
// Bit-exact vs jnp.argmax first-index tie semantics.
// cbL = codebook + (L*GDIM+g0)*64 + part (precomputed); offset = j*64 + gidx*4.
#define DO_LUT(v, cbL, j, accv)                                               \
    {                                                                         \
        float m = (v).x; int mi = 0;                                          \
        if ((v).y > m) { m = (v).y; mi = 1; }                                 \
        if ((v).z > m) { m = (v).z; mi = 2; }                                 \
        if ((v).w > m) { m = (v).w; mi = 3; }                                 \
        float q = fmaxf(m, __shfl_xor_sync(0xffffffffu, m, 1));               \
        q = fmaxf(q, __shfl_xor_sync(0xffffffffu, q, 2));                     \
        const unsigned bal = __ballot_sync(0xffffffffu, m == q);              \
        const unsigned nib = (bal >> (lane & 28)) & 0xFu;                     \
        const int wl = (lane & 28) + (__ffs(nib) - 1);                        \
        const int wmi = __shfl_sync(0xffffffffu, mi, wl);                     \
        const int gidx = ((wl & 3) << 2) | wmi;                               \
        (accv) += __ldg((cbL) + ((j) << 6) + (gidx << 2));                    \
    }

__global__ void __launch_bounds__(NTHREADS, 8)
recon_kernel(const float* __restrict__ gate,
             const float* __restrict__ codebook,
             const float* __restrict__ scales,
             const int*   __restrict__ zeros,
             float*       __restrict__ out)
{
    __shared__ float otile[OTILE * SROW];   // 9216 B

    const int tid    = threadIdx.x;
    const int wid    = tid >> 5;
    const int lane   = tid & 31;
    const int part   = lane & 3;              // which 16B quarter of the 64B gate row
    const int o_sub  = lane >> 2;             // which of the warp's 8 o's

    const int o0_blk = blockIdx.x * OTILE;
    const int o0     = o0_blk + wid * O_PER_WARP;   // warp's first o
    const int o      = o0 + o_sub;
    const int o_loc  = wid * O_PER_WARP + o_sub;    // 0..63 within block
    const int g0     = blockIdx.y * GTILE_J;
    const int ng     = blockIdx.y >> 2;       // quant group (8*4 = 32 g's per group)

    const float sc   = scales[o * NGRP + ng];
    const float bias = -((float)zeros[o * NGRP + ng]) * sc;  // out = acc*sc + bias

    // Gate base pointers (float4 units). For fixed (l,g): warp covers
    // o0..o0+7 -> one contiguous 512B chunk; lane q reads float4 #q.
    const float4* gp0 = reinterpret_cast<const float4*>(gate) +
        (((size_t)0 * GDIM + g0) * OUTF + o0) * (SLUT / 4) + lane;
    const float4* gp1 = reinterpret_cast<const float4*>(gate) +
        (((size_t)1 * GDIM + g0) * OUTF + o0) * (SLUT / 4) + lane;
    const float4* gp2 = reinterpret_cast<const float4*>(gate) +
        (((size_t)2 * GDIM + g0) * OUTF + o0) * (SLUT / 4) + lane;
    const size_t gstep = (size_t)OUTF * SLUT / 4;   // 16384 float4 per g

    // Per-LUT codebook base for this block's g-range and this lane's part.
    const float* cb0 = codebook + ((size_t)(0 * GDIM) + g0) * (SLUT * VEC) + part;
    const float* cb1 = codebook + ((size_t)(1 * GDIM) + g0) * (SLUT * VEC) + part;
    const float* cb2 = codebook + ((size_t)(2 * GDIM) + g0) * (SLUT * VEC) + part;

    float* myrow = &otile[o_loc * SROW + part];     // + j*4 per step

    #pragma unroll 2
    for (int j = 0; j < GTILE_J; ++j) {
        // Issue all three contiguous 512B streaming loads up front
        const float4 v0 = __ldcs(gp0 + (size_t)j * gstep);
        const float4 v1 = __ldcs(gp1 + (size_t)j * gstep);
        const float4 v2 = __ldcs(gp2 + (size_t)j * gstep);

        float acc = 0.0f;
        DO_LUT(v0, cb0, j, acc)
        DO_LUT(v1, cb1, j, acc)
        DO_LUT(v2, cb2, j, acc)

        // Stage into smem (conflict-free); flushed coalesced at block end.
        myrow[j * 4] = fmaf(acc, sc, bias);
    }

    __syncthreads();

    // Flush: 512 float4 slots; thread t handles slots t and t+256.
    // Lanes 0..7 of each 8-lane group share one o row, j=0..7 -> one full,
    // aligned 128B global line per group: zero partial sectors, no RMW.
    #pragma unroll
    for (int t = 0; t < 2; ++t) {
        const int idx = tid + t * NTHREADS;    // 0..511
        const int ol  = idx >> 3;              // 0..63
        const int jj  = idx & 7;               // 0..7
        const float4 v = *reinterpret_cast<const float4*>(&otile[ol * SROW + jj * 4]);
        __stcs(reinterpret_cast<float4*>(out) +
               (size_t)(o0_blk + ol) * (GDIM) + g0 + jj, v);
    }
}

extern "C" void kernel_launch(void* const* d_in, const int* in_sizes, int n_in,
                              void* d_out, int out_size) {
    const float* gate     = (const float*)d_in[0];  // [3,1024,4096,16] f32
    const float* codebook = (const float*)d_in[1];  // [3,1024,16,4]   f32
    const float* scales   = (const float*)d_in[2];  // [4096,32]       f32
    const int*   zeros    = (const int*)  d_in[3];  // [4096,32]       i32
    float*       out      = (float*)d_out;          // [4096,4096]     f32

    (void)in_sizes; (void)n_in; (void)out_size;

    dim3 grid(OUTF / OTILE, GDIM / GTILE_J);   // (64, 128) = 8192 blocks
    recon_kernel<<<grid, NTHREADS>>>(gate, codebook, scales, zeros, out);
}

// round 15
// speedup vs baseline: 1.0453x; 1.0146x over previous
#include <cuda_runtime.h>
#include <cstdint>
#include <cstddef>

// Problem constants
#define NUM_LUT 3
#define GDIM    1024      // G = IN_F / VEC
#define OUTF    4096
#define SLUT    16
#define VEC     4
#define NGRP    32        // NG = IN_F / GROUP (GROUP = 32 g's)

// Tiling: block = 8 warps; each warp owns 8 consecutive o's; block loops 8 g's.
// (GTILE_J=8 frozen: R10 showed 16 regresses via longer barrier phases.)
#define NTHREADS 256
#define O_PER_WARP 8
#define OTILE (8 * O_PER_WARP)   // 64 o per block
#define GTILE_J 8                // g's per block (8 | 32 -> single quant group per block)

// Output staging tile: [64 o][stride 36 words]; row holds 8 j * 4 part = 32
// floats + 4 pad words. Stride 36 => STS bank = (o_sub*4 + part) mod 32,
// distinct for all 32 lanes of a warp (conflict-free); flush phases likewise.
#define SROW 36

// Per-LUT argmax over 16 gate values spread across a quad (4 floats/lane):
//  1) local max via 2-level fmaxf tree (depth 2 -> shfl chain starts early);
//     local index resolved by an ordered equality chain IN PARALLEL with the
//     shfl chain (first match = first occurrence, exact).
//  2) quad max by VALUE only: 2x shfl.bfly + fmaxf (bit-exact, NaN-free data)
//  3) ballot (full-warp uniform mask) of lanes matching the quad max;
//     lowest set lane in my quad = exact first-occurrence winner
//  4) one shfl.idx fetches the winner's local index
// Bit-exact vs jnp.argmax first-index tie semantics.
#define DO_LUT(v, L, g, accv)                                                 \
    {                                                                         \
        const float m = fmaxf(fmaxf((v).x, (v).y), fmaxf((v).z, (v).w));      \
        float q = fmaxf(m, __shfl_xor_sync(0xffffffffu, m, 1));               \
        q = fmaxf(q, __shfl_xor_sync(0xffffffffu, q, 2));                     \
        const int mi = ((v).x == m) ? 0 : ((v).y == m) ? 1                    \
                     : ((v).z == m) ? 2 : 3;                                  \
        const unsigned bal = __ballot_sync(0xffffffffu, m == q);              \
        const unsigned nib = (bal >> (lane & 28)) & 0xFu;                     \
        const int wl = (lane & 28) + (__ffs(nib) - 1);                        \
        const int wmi = __shfl_sync(0xffffffffu, mi, wl);                     \
        const int gidx = ((wl & 3) << 2) | wmi;                               \
        (accv) += __ldg(cbk + (((size_t)(L) * GDIM + (g)) * SLUT + gidx) * VEC + part); \
    }

__global__ void __launch_bounds__(NTHREADS, 8)
recon_kernel(const float* __restrict__ gate,
             const float* __restrict__ codebook,
             const float* __restrict__ scales,
             const int*   __restrict__ zeros,
             float*       __restrict__ out)
{
    __shared__ float otile[OTILE * SROW];   // 9216 B

    const int tid    = threadIdx.x;
    const int wid    = tid >> 5;
    const int lane   = tid & 31;
    const int part   = lane & 3;              // which 16B quarter of the 64B gate row
    const int o_sub  = lane >> 2;             // which of the warp's 8 o's

    const int o0_blk = blockIdx.x * OTILE;
    const int o0     = o0_blk + wid * O_PER_WARP;   // warp's first o
    const int o      = o0 + o_sub;
    const int o_loc  = wid * O_PER_WARP + o_sub;    // 0..63 within block
    const int g0     = blockIdx.y * GTILE_J;
    const int ng     = blockIdx.y >> 2;       // quant group (8*4 = 32 g's per group)

    const float sc   = scales[o * NGRP + ng];
    const float bias = -((float)zeros[o * NGRP + ng]) * sc;  // out = acc*sc + bias

    // Gate base pointers (float4 units). For fixed (l,g): warp covers
    // o0..o0+7 -> one contiguous 512B chunk; lane q reads float4 #q.
    const float4* gp0 = reinterpret_cast<const float4*>(gate) +
        (((size_t)0 * GDIM + g0) * OUTF + o0) * (SLUT / 4) + lane;
    const float4* gp1 = reinterpret_cast<const float4*>(gate) +
        (((size_t)1 * GDIM + g0) * OUTF + o0) * (SLUT / 4) + lane;
    const float4* gp2 = reinterpret_cast<const float4*>(gate) +
        (((size_t)2 * GDIM + g0) * OUTF + o0) * (SLUT / 4) + lane;
    const size_t gstep = (size_t)OUTF * SLUT / 4;   // 16384 float4 per g

    const float* cbk = codebook;

    float* myrow = &otile[o_loc * SROW + part];     // + j*4 per step

    #pragma unroll 2
    for (int j = 0; j < GTILE_J; ++j) {
        const int g = g0 + j;

        // Issue all three contiguous 512B streaming loads up front
        const float4 v0 = __ldcs(gp0 + (size_t)j * gstep);
        const float4 v1 = __ldcs(gp1 + (size_t)j * gstep);
        const float4 v2 = __ldcs(gp2 + (size_t)j * gstep);

        float acc = 0.0f;
        DO_LUT(v0, 0, g, acc)
        DO_LUT(v1, 1, g, acc)
        DO_LUT(v2, 2, g, acc)

        // Stage into smem (conflict-free); flushed coalesced at block end.
        myrow[j * 4] = fmaf(acc, sc, bias);
    }

    __syncthreads();

    // Flush: 512 float4 slots; thread t handles slots t and t+256.
    // Lanes 0..7 of each 8-lane group share one o row, j=0..7 -> one full,
    // aligned 128B global line per group: zero partial sectors, no RMW.
    #pragma unroll
    for (int t = 0; t < 2; ++t) {
        const int idx = tid + t * NTHREADS;    // 0..511
        const int ol  = idx >> 3;              // 0..63
        const int jj  = idx & 7;               // 0..7
        const float4 v = *reinterpret_cast<const float4*>(&otile[ol * SROW + jj * 4]);
        __stcs(reinterpret_cast<float4*>(out) +
               (size_t)(o0_blk + ol) * (GDIM) + g0 + jj, v);
    }
}

extern "C" void kernel_launch(void* const* d_in, const int* in_sizes, int n_in,
                              void* d_out, int out_size) {
    const float* gate     = (const float*)d_in[0];  // [3,1024,4096,16] f32
    const float* codebook = (const float*)d_in[1];  // [3,1024,16,4]   f32
    const float* scales   = (const float*)d_in[2];  // [4096,32]       f32
    const int*   zeros    = (const int*)  d_in[3];  // [4096,32]       i32
    float*       out      = (float*)d_out;          // [4096,4096]     f32

    (void)in_sizes; (void)n_in; (void)out_size;

    dim3 grid(OUTF / OTILE, GDIM / GTILE_J);   // (64, 128) = 8192 blocks
    recon_kernel<<<grid, NTHREADS>>>(gate, codebook, scales, zeros, out);
}

// round 16
// speedup vs baseline: 1.0466x; 1.0012x over previous
#include <cuda_runtime.h>
#include <cstdint>
#include <cstddef>

// Problem constants
#define NUM_LUT 3
#define GDIM    1024      // G = IN_F / VEC
#define OUTF    4096
#define SLUT    16
#define VEC     4
#define NGRP    32        // NG = IN_F / GROUP (GROUP = 32 g's)

// Tiling: block = 8 warps; each warp owns 8 consecutive o's; block loops 8 g's.
// (GTILE_J=8 frozen: R10 showed 16 regresses via longer barrier phases.)
#define NTHREADS 256
#define O_PER_WARP 8
#define OTILE (8 * O_PER_WARP)   // 64 o per block
#define GTILE_J 8                // g's per block (8 | 32 -> single quant group per block)

// Output staging tile: [64 o][stride 36 words]; row holds 8 j * 4 part = 32
// floats + 4 pad words. Stride 36 => STS bank = (o_sub*4 + part) mod 32,
// distinct for all 32 lanes of a warp (conflict-free). Flush is WARP-LOCAL:
// each warp stages and flushes only its own 8 rows (no __syncthreads).
#define SROW 36

// Per-LUT argmax over 16 gate values spread across a quad (4 floats/lane):
//  1) local max via 2-level fmaxf tree; local index via ordered equality
//     chain resolved IN PARALLEL with the shfl chain (first match = first
//     occurrence, exact).
//  2) quad max by VALUE only: 2x shfl.bfly + fmaxf (bit-exact, NaN-free data)
//  3) ballot (full-warp uniform mask) of lanes matching the quad max;
//     lowest set lane in my quad = exact first-occurrence winner
//  4) one shfl.idx fetches the winner's local index
// Bit-exact vs jnp.argmax first-index tie semantics.
#define DO_LUT(v, L, g, accv)                                                 \
    {                                                                         \
        const float m = fmaxf(fmaxf((v).x, (v).y), fmaxf((v).z, (v).w));      \
        float q = fmaxf(m, __shfl_xor_sync(0xffffffffu, m, 1));               \
        q = fmaxf(q, __shfl_xor_sync(0xffffffffu, q, 2));                     \
        const int mi = ((v).x == m) ? 0 : ((v).y == m) ? 1                    \
                     : ((v).z == m) ? 2 : 3;                                  \
        const unsigned bal = __ballot_sync(0xffffffffu, m == q);              \
        const unsigned nib = (bal >> (lane & 28)) & 0xFu;                     \
        const int wl = (lane & 28) + (__ffs(nib) - 1);                        \
        const int wmi = __shfl_sync(0xffffffffu, mi, wl);                     \
        const int gidx = ((wl & 3) << 2) | wmi;                               \
        (accv) += __ldg(cbk + (((size_t)(L) * GDIM + (g)) * SLUT + gidx) * VEC + part); \
    }

__global__ void __launch_bounds__(NTHREADS, 8)
recon_kernel(const float* __restrict__ gate,
             const float* __restrict__ codebook,
             const float* __restrict__ scales,
             const int*   __restrict__ zeros,
             float*       __restrict__ out)
{
    __shared__ float otile[OTILE * SROW];   // 9216 B

    const int tid    = threadIdx.x;
    const int wid    = tid >> 5;
    const int lane   = tid & 31;
    const int part   = lane & 3;              // which 16B quarter of the 64B gate row
    const int o_sub  = lane >> 2;             // which of the warp's 8 o's

    const int o0_blk = blockIdx.x * OTILE;
    const int o0     = o0_blk + wid * O_PER_WARP;   // warp's first o
    const int o      = o0 + o_sub;
    const int o_loc  = wid * O_PER_WARP + o_sub;    // 0..63 within block
    const int g0     = blockIdx.y * GTILE_J;
    const int ng     = blockIdx.y >> 2;       // quant group (8*4 = 32 g's per group)

    const float sc   = scales[o * NGRP + ng];
    const float bias = -((float)zeros[o * NGRP + ng]) * sc;  // out = acc*sc + bias

    // Gate base pointers (float4 units). For fixed (l,g): warp covers
    // o0..o0+7 -> one contiguous 512B chunk; lane q reads float4 #q.
    const float4* gp0 = reinterpret_cast<const float4*>(gate) +
        (((size_t)0 * GDIM + g0) * OUTF + o0) * (SLUT / 4) + lane;
    const float4* gp1 = reinterpret_cast<const float4*>(gate) +
        (((size_t)1 * GDIM + g0) * OUTF + o0) * (SLUT / 4) + lane;
    const float4* gp2 = reinterpret_cast<const float4*>(gate) +
        (((size_t)2 * GDIM + g0) * OUTF + o0) * (SLUT / 4) + lane;
    const size_t gstep = (size_t)OUTF * SLUT / 4;   // 16384 float4 per g

    const float* cbk = codebook;

    float* myrow = &otile[o_loc * SROW + part];     // + j*4 per step

    #pragma unroll 2
    for (int j = 0; j < GTILE_J; ++j) {
        const int g = g0 + j;

        // Issue all three contiguous 512B streaming loads up front
        const float4 v0 = __ldcs(gp0 + (size_t)j * gstep);
        const float4 v1 = __ldcs(gp1 + (size_t)j * gstep);
        const float4 v2 = __ldcs(gp2 + (size_t)j * gstep);

        float acc = 0.0f;
        DO_LUT(v0, 0, g, acc)
        DO_LUT(v1, 1, g, acc)
        DO_LUT(v2, 2, g, acc)

        // Stage into smem (conflict-free); flushed warp-locally below.
        myrow[j * 4] = fmaf(acc, sc, bias);
    }

    // Warp-local flush: this warp produced rows [wid*8, wid*8+8); only its own
    // lanes read them back, so __syncwarp ordering suffices — no block barrier.
    __syncwarp();

    const int wrow0 = wid * O_PER_WARP;
    #pragma unroll
    for (int t = 0; t < 2; ++t) {
        const int idx = lane + t * 32;         // 0..63 within warp tile
        const int ol  = wrow0 + (idx >> 3);    // this warp's o row
        const int jj  = idx & 7;               // 0..7
        // 8-lane group reads one full smem row (8 x 16B = 32 banks, conflict-
        // free) and writes one full, aligned 128B global line: no RMW.
        const float4 v = *reinterpret_cast<const float4*>(&otile[ol * SROW + jj * 4]);
        __stcs(reinterpret_cast<float4*>(out) +
               (size_t)(o0_blk + ol) * (GDIM) + g0 + jj, v);
    }
}

extern "C" void kernel_launch(void* const* d_in, const int* in_sizes, int n_in,
                              void* d_out, int out_size) {
    const float* gate     = (const float*)d_in[0];  // [3,1024,4096,16] f32
    const float* codebook = (const float*)d_in[1];  // [3,1024,16,4]   f32
    const float* scales   = (const float*)d_in[2];  // [4096,32]       f32
    const int*   zeros    = (const int*)  d_in[3];  // [4096,32]       i32
    float*       out      = (float*)d_out;          // [4096,4096]     f32

    (void)in_sizes; (void)n_in; (void)out_size;

    dim3 grid(OUTF / OTILE, GDIM / GTILE_J);   // (64, 128) = 8192 blocks
    recon_kernel<<<grid, NTHREADS>>>(gate, codebook, scales, zeros, out);
}